// round 1
// baseline (speedup 1.0000x reference)
#include <cuda_runtime.h>
#include <cstdint>

#define B_DIM 512
#define F_DIM 784
#define R_DIM 512
#define C_DIM 16
#define D_DIM 49
#define HALF_LOG_2PI 0.9189385332046727f

// Scratch (allocation-free rule: __device__ globals)
__device__ float g_A[R_DIM * C_DIM * D_DIM];     // [r][d][c] layout: -0.5/scale^2
__device__ float g_Bc[R_DIM * C_DIM * D_DIM];    // [r][d][c] layout: loc/scale^2
__device__ float g_base[R_DIM * C_DIM];          // [r][c]
__device__ float g_xT[F_DIM * B_DIM];            // [f][b]
__device__ float g_xg[R_DIM * D_DIM * B_DIM];    // [r*49+d][b]

// ---------------------------------------------------------------------------
// Kernel 1: per-(r,c,d) coefficients + per-(r,c) base term.
// Writes A/B in [r][d][c] layout so the main kernel's shared tiles are
// directly float4-loadable along c. Deterministic reduction (no atomics).
// ---------------------------------------------------------------------------
__global__ void __launch_bounds__(256) prep_kernel(const float* __restrict__ loc,
                                                   const float* __restrict__ scale) {
    int r = blockIdx.x;
    int t = threadIdx.x;
    __shared__ float s_contrib[C_DIM * D_DIM];   // [c][d]
    for (int idx = t; idx < C_DIM * D_DIM; idx += 256) {
        int d = idx >> 4;          // idx = d*16 + c
        int c = idx & 15;
        int src = r * (C_DIM * D_DIM) + c * D_DIM + d;
        float lc = loc[src];
        float sc = scale[src];
        float A, Bv, contrib;
        if (sc > 0.0f) {
            float inv = 1.0f / sc;
            float w = inv * inv;
            A = -0.5f * w;
            Bv = w * lc;
            contrib = -0.5f * w * lc * lc - logf(sc) - HALF_LOG_2PI;
        } else {
            // reference: logp is NaN here -> zeroed contribution
            A = 0.0f; Bv = 0.0f; contrib = 0.0f;
        }
        g_A[r * 784 + idx]  = A;
        g_Bc[r * 784 + idx] = Bv;
        s_contrib[c * D_DIM + d] = contrib;
    }
    __syncthreads();
    if (t < C_DIM) {
        float s = 0.0f;
        #pragma unroll
        for (int d = 0; d < D_DIM; ++d) s += s_contrib[t * D_DIM + d];
        g_base[r * C_DIM + t] = s;
    }
}

// ---------------------------------------------------------------------------
// Kernel 2: transpose x[b][f] -> xT[f][b] so the gather can be coalesced.
// ---------------------------------------------------------------------------
__global__ void __launch_bounds__(256) transpose_kernel(const float* __restrict__ x) {
    __shared__ float tile[32][33];
    int fx = blockIdx.x * 32 + threadIdx.x;
    #pragma unroll
    for (int k = 0; k < 32; k += 8) {
        int b = blockIdx.y * 32 + threadIdx.y + k;
        if (fx < F_DIM) tile[threadIdx.y + k][threadIdx.x] = x[b * F_DIM + fx];
    }
    __syncthreads();
    int b_out = blockIdx.y * 32 + threadIdx.x;
    #pragma unroll
    for (int k = 0; k < 32; k += 8) {
        int f = blockIdx.x * 32 + threadIdx.y + k;
        if (f < F_DIM) g_xT[f * B_DIM + b_out] = tile[threadIdx.x][threadIdx.y + k];
    }
}

// ---------------------------------------------------------------------------
// Kernel 3: gather xg[r*49+d][b] = xT[mask[r*49+d]][b].
// One block per (r,d); fully coalesced float4 read AND write.
// ---------------------------------------------------------------------------
__global__ void __launch_bounds__(128) gather_kernel(const int* __restrict__ mask) {
    int rd = blockIdx.x;                 // 0 .. R*D-1
    int f  = __ldg(&mask[rd]);
    const float4* src = reinterpret_cast<const float4*>(g_xT) + f * (B_DIM / 4);
    float4* dst = reinterpret_cast<float4*>(g_xg) + rd * (B_DIM / 4);
    dst[threadIdx.x] = src[threadIdx.x];
}

// ---------------------------------------------------------------------------
// Kernel 4: main compute. Block = (r, 128-wide b tile). 128 threads.
// Thread tile: 4 b x 4 c. Per d: 3x LDS.128 (x, A, B) + 32 FFMA.
// ---------------------------------------------------------------------------
#define XS_STRIDE 132   // pad 128 -> 132 (still /4) for conflict-free LDS.128

__global__ void __launch_bounds__(128) main_kernel(float* __restrict__ out) {
    int r  = blockIdx.x;
    int b0 = blockIdx.y * 128;
    int tid = threadIdx.x;

    __shared__ float xs[D_DIM * XS_STRIDE];
    __shared__ float As[C_DIM * D_DIM];   // [d][c]
    __shared__ float Bs[C_DIM * D_DIM];   // [d][c]

    // coefficient tiles (already in [d][c] layout in global)
    {
        const float4* Ag = reinterpret_cast<const float4*>(g_A  + r * 784);
        const float4* Bg = reinterpret_cast<const float4*>(g_Bc + r * 784);
        float4* As4 = reinterpret_cast<float4*>(As);
        float4* Bs4 = reinterpret_cast<float4*>(Bs);
        for (int i = tid; i < 196; i += 128) { As4[i] = Ag[i]; Bs4[i] = Bg[i]; }
    }
    // x tile: 49 rows of 128 floats from xg
    {
        const float4* xsrc = reinterpret_cast<const float4*>(g_xg)
                           + (size_t)r * D_DIM * (B_DIM / 4) + (b0 >> 2);
        for (int i = tid; i < D_DIM * 32; i += 128) {
            int d = i >> 5, q = i & 31;
            *reinterpret_cast<float4*>(xs + d * XS_STRIDE + q * 4) = xsrc[d * (B_DIM / 4) + q];
        }
    }
    __syncthreads();

    int g = tid >> 2;    // 0..31  -> b = b0 + 4g + i
    int h = tid & 3;     // 0..3   -> c = 4h + j

    float acc[4][4];
    #pragma unroll
    for (int i = 0; i < 4; ++i)
        #pragma unroll
        for (int j = 0; j < 4; ++j) acc[i][j] = 0.0f;

    const float* xp = xs + 4 * g;
    const float* ap = As + 4 * h;
    const float* bp = Bs + 4 * h;

    #pragma unroll 7
    for (int d = 0; d < D_DIM; ++d) {
        float4 xv = *reinterpret_cast<const float4*>(xp + d * XS_STRIDE);
        float4 av = *reinterpret_cast<const float4*>(ap + d * C_DIM);
        float4 bv = *reinterpret_cast<const float4*>(bp + d * C_DIM);
        float xr[4] = {xv.x, xv.y, xv.z, xv.w};
        float ar[4] = {av.x, av.y, av.z, av.w};
        float br[4] = {bv.x, bv.y, bv.z, bv.w};
        #pragma unroll
        for (int j = 0; j < 4; ++j)
            #pragma unroll
            for (int i = 0; i < 4; ++i) {
                float t = fmaf(ar[j], xr[i], br[j]);
                acc[i][j] = fmaf(xr[i], t, acc[i][j]);
            }
    }

    float4 base = *reinterpret_cast<const float4*>(g_base + r * C_DIM + 4 * h);
    float bb[4] = {base.x, base.y, base.z, base.w};

    #pragma unroll
    for (int i = 0; i < 4; ++i) {
        int b = b0 + 4 * g + i;
        float4 o;
        o.x = acc[i][0] + bb[0];
        o.y = acc[i][1] + bb[1];
        o.z = acc[i][2] + bb[2];
        o.w = acc[i][3] + bb[3];
        *reinterpret_cast<float4*>(out + (size_t)b * (R_DIM * C_DIM) + r * C_DIM + 4 * h) = o;
    }
}

// ---------------------------------------------------------------------------
extern "C" void kernel_launch(void* const* d_in, const int* in_sizes, int n_in,
                              void* d_out, int out_size) {
    const float* x     = (const float*)d_in[0];
    const int*   mask  = (const int*)d_in[1];
    const float* loc   = (const float*)d_in[2];
    const float* scale = (const float*)d_in[3];
    float* out = (float*)d_out;

    prep_kernel<<<R_DIM, 256>>>(loc, scale);
    transpose_kernel<<<dim3((F_DIM + 31) / 32, B_DIM / 32), dim3(32, 8)>>>(x);
    gather_kernel<<<R_DIM * D_DIM, 128>>>(mask);
    main_kernel<<<dim3(R_DIM, B_DIM / 128), 128>>>(out);
}

// round 2
// speedup vs baseline: 1.4928x; 1.4928x over previous
#include <cuda_runtime.h>
#include <cstdint>

#define B_DIM 512
#define F_DIM 784
#define R_DIM 512
#define C_DIM 16
#define D_DIM 49
#define HALF_LOG_2PI 0.9189385332046727f

// Scratch (allocation-free rule: __device__ globals)
__device__ float g_A2[R_DIM * D_DIM * C_DIM * 2];   // [r][d][c] duplicated f32x2: -0.5/scale^2
__device__ float g_B2[R_DIM * D_DIM * C_DIM * 2];   // [r][d][c] duplicated f32x2: loc/scale^2
__device__ float g_base[R_DIM * C_DIM];             // [r][c]
__device__ float g_xT[F_DIM * B_DIM];               // [f][b]

// ---------------------------------------------------------------------------
// packed f32x2 FMA (Blackwell FFMA2 — only reachable via PTX)
// ---------------------------------------------------------------------------
__device__ __forceinline__ unsigned long long fma2(unsigned long long a,
                                                   unsigned long long b,
                                                   unsigned long long c) {
    unsigned long long d;
    asm("fma.rn.f32x2 %0, %1, %2, %3;" : "=l"(d) : "l"(a), "l"(b), "l"(c));
    return d;
}
__device__ __forceinline__ void unpack2(unsigned long long v, float& lo, float& hi) {
    unsigned int l, h;
    asm("mov.b64 {%0, %1}, %2;" : "=r"(l), "=r"(h) : "l"(v));
    lo = __uint_as_float(l);
    hi = __uint_as_float(h);
}

// ---------------------------------------------------------------------------
// Kernel 1: coefficients (duplicated into f32x2 lanes) + per-(r,c) base term.
// ---------------------------------------------------------------------------
__global__ void __launch_bounds__(256) prep_kernel(const float* __restrict__ loc,
                                                   const float* __restrict__ scale) {
    int r = blockIdx.x;
    int t = threadIdx.x;
    __shared__ float s_contrib[C_DIM * D_DIM];   // [c][d]
    for (int idx = t; idx < C_DIM * D_DIM; idx += 256) {
        int d = idx >> 4;          // idx = d*16 + c
        int c = idx & 15;
        int src = r * (C_DIM * D_DIM) + c * D_DIM + d;
        float lc = loc[src];
        float sc = scale[src];
        float A, Bv, contrib;
        if (sc > 0.0f) {
            float inv = 1.0f / sc;
            float w = inv * inv;
            A = -0.5f * w;
            Bv = w * lc;
            contrib = -0.5f * w * lc * lc - logf(sc) - HALF_LOG_2PI;
        } else {
            A = 0.0f; Bv = 0.0f; contrib = 0.0f;   // reference zeroes NaN logp
        }
        reinterpret_cast<float2*>(g_A2)[r * 784 + idx] = make_float2(A, A);
        reinterpret_cast<float2*>(g_B2)[r * 784 + idx] = make_float2(Bv, Bv);
        s_contrib[c * D_DIM + d] = contrib;
    }
    __syncthreads();
    if (t < C_DIM) {
        float s = 0.0f;
        #pragma unroll
        for (int d = 0; d < D_DIM; ++d) s += s_contrib[t * D_DIM + d];
        g_base[r * C_DIM + t] = s;
    }
}

// ---------------------------------------------------------------------------
// Kernel 2: transpose x[b][f] -> xT[f][b] (xT is 1.6MB -> stays L2-resident).
// ---------------------------------------------------------------------------
__global__ void __launch_bounds__(256) transpose_kernel(const float* __restrict__ x) {
    __shared__ float tile[32][33];
    int fx = blockIdx.x * 32 + threadIdx.x;
    #pragma unroll
    for (int k = 0; k < 32; k += 8) {
        int b = blockIdx.y * 32 + threadIdx.y + k;
        if (fx < F_DIM) tile[threadIdx.y + k][threadIdx.x] = x[b * F_DIM + fx];
    }
    __syncthreads();
    int b_out = blockIdx.y * 32 + threadIdx.x;
    #pragma unroll
    for (int k = 0; k < 32; k += 8) {
        int f = blockIdx.x * 32 + threadIdx.y + k;
        if (f < F_DIM) g_xT[f * B_DIM + b_out] = tile[threadIdx.x][threadIdx.y + k];
    }
}

// ---------------------------------------------------------------------------
// Kernel 3: main compute, gather fused. Block = (r, 256-wide b tile),
// 128 threads, thread tile 8b x 4c (as 4 f32x2 b-pairs x 4 c).
// d processed in 7 chunks of 7, double-buffered smem; x gathered straight
// from L2-resident xT. Inner loop per d: 6x LDS.128 + 32x FFMA2.
// ---------------------------------------------------------------------------
#define XST 264          // 256 + 8 pad, keeps float4 alignment, avoids conflicts
#define DCHUNK 7
#define NCHUNK 7

__global__ void __launch_bounds__(128) main_kernel(const int* __restrict__ mask,
                                                   float* __restrict__ out) {
    int r   = blockIdx.x;
    int tid = threadIdx.x;
    int bq0 = blockIdx.y * 64;              // float4 offset into a 512-float b row

    __shared__ __align__(16) float sA2[D_DIM * 32];       // [d][c] dup pairs
    __shared__ __align__(16) float sB2[D_DIM * 32];
    __shared__ __align__(16) float xs[2][DCHUNK * XST];
    __shared__ int smask[D_DIM];

    if (tid < D_DIM) smask[tid] = mask[r * D_DIM + tid];
    {
        const float4* Ag = reinterpret_cast<const float4*>(g_A2 + r * (D_DIM * 32));
        const float4* Bg = reinterpret_cast<const float4*>(g_B2 + r * (D_DIM * 32));
        float4* As4 = reinterpret_cast<float4*>(sA2);
        float4* Bs4 = reinterpret_cast<float4*>(sB2);
        #pragma unroll
        for (int i = 0; i < 4; ++i) {
            int idx = tid + i * 128;
            if (idx < 392) { As4[idx] = Ag[idx]; Bs4[idx] = Bg[idx]; }
        }
    }
    __syncthreads();    // smask + coeffs ready

    const float4* xT4 = reinterpret_cast<const float4*>(g_xT);
    float4 pf[4];

    // prefetch chunk 0
    #pragma unroll
    for (int s = 0; s < 4; ++s) {
        int idx = tid + s * 128;
        if (idx < DCHUNK * 64) {
            int dl = idx >> 6, q = idx & 63;
            pf[s] = xT4[smask[dl] * 128 + bq0 + q];
        }
    }
    #pragma unroll
    for (int s = 0; s < 4; ++s) {
        int idx = tid + s * 128;
        if (idx < DCHUNK * 64) {
            int dl = idx >> 6, q = idx & 63;
            *reinterpret_cast<float4*>(&xs[0][dl * XST + q * 4]) = pf[s];
        }
    }

    int g = tid >> 2;    // 0..31 -> b = b0 + 8g + 0..7
    int h = tid & 3;     // 0..3  -> c = 4h + 0..3

    unsigned long long acc[4][4];
    #pragma unroll
    for (int i = 0; i < 4; ++i)
        #pragma unroll
        for (int j = 0; j < 4; ++j) acc[i][j] = 0ull;   // (0.0f, 0.0f)

    for (int k = 0; k < NCHUNK; ++k) {
        __syncthreads();                         // buf[k&1] filled
        if (k < NCHUNK - 1) {                    // issue next chunk's LDGs early
            int d0n = (k + 1) * DCHUNK;
            #pragma unroll
            for (int s = 0; s < 4; ++s) {
                int idx = tid + s * 128;
                if (idx < DCHUNK * 64) {
                    int dl = idx >> 6, q = idx & 63;
                    pf[s] = xT4[smask[d0n + dl] * 128 + bq0 + q];
                }
            }
        }

        const float* xb = &xs[k & 1][g * 8];
        const float* Ab = sA2 + k * (DCHUNK * 32) + h * 8;
        const float* Bb = sB2 + k * (DCHUNK * 32) + h * 8;

        #pragma unroll
        for (int dd = 0; dd < DCHUNK; ++dd) {
            ulonglong2 xa = *reinterpret_cast<const ulonglong2*>(xb + dd * XST);
            ulonglong2 xc = *reinterpret_cast<const ulonglong2*>(xb + dd * XST + 4);
            ulonglong2 aa = *reinterpret_cast<const ulonglong2*>(Ab + dd * 32);
            ulonglong2 ac = *reinterpret_cast<const ulonglong2*>(Ab + dd * 32 + 4);
            ulonglong2 ba = *reinterpret_cast<const ulonglong2*>(Bb + dd * 32);
            ulonglong2 bc = *reinterpret_cast<const ulonglong2*>(Bb + dd * 32 + 4);
            unsigned long long x2[4] = {xa.x, xa.y, xc.x, xc.y};
            unsigned long long a2[4] = {aa.x, aa.y, ac.x, ac.y};
            unsigned long long b2[4] = {ba.x, ba.y, bc.x, bc.y};
            #pragma unroll
            for (int j = 0; j < 4; ++j)
                #pragma unroll
                for (int i = 0; i < 4; ++i) {
                    unsigned long long t = fma2(a2[j], x2[i], b2[j]);
                    acc[i][j] = fma2(x2[i], t, acc[i][j]);
                }
        }

        if (k < NCHUNK - 1) {
            int b1 = (k + 1) & 1;
            #pragma unroll
            for (int s = 0; s < 4; ++s) {
                int idx = tid + s * 128;
                if (idx < DCHUNK * 64) {
                    int dl = idx >> 6, q = idx & 63;
                    *reinterpret_cast<float4*>(&xs[b1][dl * XST + q * 4]) = pf[s];
                }
            }
        }
    }

    // epilogue: unpack pairs, add base, store
    float4 bb4 = *reinterpret_cast<const float4*>(g_base + r * C_DIM + h * 4);
    float bb[4] = {bb4.x, bb4.y, bb4.z, bb4.w};
    int b0 = blockIdx.y * 256 + g * 8;

    #pragma unroll
    for (int i = 0; i < 4; ++i) {
        float lo[4], hi[4];
        #pragma unroll
        for (int j = 0; j < 4; ++j) unpack2(acc[i][j], lo[j], hi[j]);
        float4 o0, o1;
        o0.x = lo[0] + bb[0]; o0.y = lo[1] + bb[1]; o0.z = lo[2] + bb[2]; o0.w = lo[3] + bb[3];
        o1.x = hi[0] + bb[0]; o1.y = hi[1] + bb[1]; o1.z = hi[2] + bb[2]; o1.w = hi[3] + bb[3];
        size_t row = (size_t)(b0 + 2 * i) * (R_DIM * C_DIM) + r * C_DIM + h * 4;
        *reinterpret_cast<float4*>(out + row) = o0;
        *reinterpret_cast<float4*>(out + row + (R_DIM * C_DIM)) = o1;
    }
}

// ---------------------------------------------------------------------------
extern "C" void kernel_launch(void* const* d_in, const int* in_sizes, int n_in,
                              void* d_out, int out_size) {
    const float* x     = (const float*)d_in[0];
    const int*   mask  = (const int*)d_in[1];
    const float* loc   = (const float*)d_in[2];
    const float* scale = (const float*)d_in[3];
    float* out = (float*)d_out;

    prep_kernel<<<R_DIM, 256>>>(loc, scale);
    transpose_kernel<<<dim3((F_DIM + 31) / 32, B_DIM / 32), dim3(32, 8)>>>(x);
    main_kernel<<<dim3(R_DIM, B_DIM / 256), 128>>>(mask, out);
}